// round 4
// baseline (speedup 1.0000x reference)
#include <cuda_runtime.h>
#include <cuda_fp16.h>
#include <math.h>
#include <mma.h>

using namespace nvcuda;

#define N_NODES   100000
#define N_EDGES   1600000
#define NUM_GRAPHS 64
#define IN_CH     128
#define HID       64
#define NUM_CLASSES 10

#define SCAN_BS   256
#define SCAN_IT   4
#define SCAN_CHUNK (SCAN_BS * SCAN_IT)
#define SCAN_NBLK ((N_NODES + SCAN_CHUNK - 1) / SCAN_CHUNK)  // 98

// ---------------- scratch ----------------
__device__ int   g_cnt[N_NODES];
__device__ int   g_fill[N_NODES];
__device__ float g_dinv[N_NODES];
__device__ int   g_rowptr[N_NODES + 1];
__device__ int2  g_edge[N_EDGES];
__device__ int   g_bsum[SCAN_NBLK];
__device__ int   g_bbase[SCAN_NBLK];
__device__ __align__(128) __half g_th[(size_t)N_NODES * HID];   // fp16 GEMM outputs (prop input)
__device__ __align__(128) float  g_h[(size_t)N_NODES * HID];    // fp32 prop outputs (GEMM input)
__device__ __align__(128) float  g_t10[(size_t)N_NODES * NUM_CLASSES];
__device__ float g_pool[NUM_GRAPHS * NUM_CLASSES];
__device__ float g_pcnt[NUM_GRAPHS];

// ---------------- degree count: 4 edges/thread ----------------
__global__ void count_kernel(const int* __restrict__ ei) {
    int t = blockIdx.x * blockDim.x + threadIdx.x;
    int e = t * 4;
    if (e + 3 < N_EDGES) {
        int4 d = *reinterpret_cast<const int4*>(ei + N_EDGES + e);
        atomicAdd(&g_cnt[d.x], 1);
        atomicAdd(&g_cnt[d.y], 1);
        atomicAdd(&g_cnt[d.z], 1);
        atomicAdd(&g_cnt[d.w], 1);
    } else {
        for (int i = e; i < N_EDGES; i++) atomicAdd(&g_cnt[ei[N_EDGES + i]], 1);
    }
}

// ---------------- pass A: per-block sums + dinv ----------------
__global__ void blocksum_dinv() {
    int b = blockIdx.x, t = threadIdx.x;
    int i0 = b * SCAN_CHUNK + t * SCAN_IT;
    int s = 0;
    #pragma unroll
    for (int i = 0; i < SCAN_IT; i++) {
        int idx = i0 + i;
        if (idx < N_NODES) {
            int c = g_cnt[idx];
            s += c;
            g_dinv[idx] = rsqrtf((float)(c + 1));
        }
    }
    #pragma unroll
    for (int off = 16; off; off >>= 1) s += __shfl_down_sync(0xffffffffu, s, off);
    __shared__ int ws[8];
    if ((t & 31) == 0) ws[t >> 5] = s;
    __syncthreads();
    if (t < 8) {
        int v = ws[t];
        #pragma unroll
        for (int off = 4; off; off >>= 1) v += __shfl_down_sync(0xffu, v, off);
        if (t == 0) g_bsum[b] = v;
    }
}

// ---------------- pass B ----------------
__global__ void scan_partials() {
    __shared__ int sm[SCAN_NBLK];
    int t = threadIdx.x;
    if (t < SCAN_NBLK) sm[t] = g_bsum[t];
    __syncthreads();
    if (t == 0) {
        int acc = 0;
        for (int i = 0; i < SCAN_NBLK; i++) { int v = sm[i]; sm[i] = acc; acc += v; }
    }
    __syncthreads();
    if (t < SCAN_NBLK) g_bbase[t] = sm[t];
}

// ---------------- pass C ----------------
__global__ void write_rowptr() {
    int b = blockIdx.x, t = threadIdx.x;
    int lane = t & 31, warp = t >> 5;
    int i0 = b * SCAN_CHUNK + t * SCAN_IT;
    int v[SCAN_IT]; int s = 0;
    #pragma unroll
    for (int i = 0; i < SCAN_IT; i++) {
        int idx = i0 + i;
        int c = (idx < N_NODES) ? g_cnt[idx] : 0;
        s += c; v[i] = s;
    }
    int x = s;
    #pragma unroll
    for (int off = 1; off < 32; off <<= 1) {
        int y = __shfl_up_sync(0xffffffffu, x, off);
        if (lane >= off) x += y;
    }
    __shared__ int ws[8];
    if (lane == 31) ws[warp] = x;
    __syncthreads();
    if (t == 0) { int a = 0; for (int w = 0; w < 8; w++) { int y = ws[w]; ws[w] = a; a += y; } }
    __syncthreads();
    int excl = g_bbase[b] + ws[warp] + (x - s);
    #pragma unroll
    for (int i = 0; i < SCAN_IT; i++) {
        int idx = i0 + i;
        if (idx < N_NODES) g_rowptr[idx + 1] = excl + v[i];
    }
    if (b == 0 && t == 0) g_rowptr[0] = 0;
}

// ---------------- CSR scatter: 2 edges/thread ----------------
__global__ void scatter_kernel(const int* __restrict__ ei) {
    int t = blockIdx.x * blockDim.x + threadIdx.x;
    int e = t * 2;
    if (e + 1 < N_EDGES) {
        int2 s2 = *reinterpret_cast<const int2*>(ei + e);
        int2 d2 = *reinterpret_cast<const int2*>(ei + N_EDGES + e);
        int pos0 = g_rowptr[d2.x] + atomicAdd(&g_fill[d2.x], 1);
        g_edge[pos0] = make_int2(s2.x, __float_as_int(g_dinv[s2.x] * g_dinv[d2.x]));
        int pos1 = g_rowptr[d2.y] + atomicAdd(&g_fill[d2.y], 1);
        g_edge[pos1] = make_int2(s2.y, __float_as_int(g_dinv[s2.y] * g_dinv[d2.y]));
    } else if (e < N_EDGES) {
        int s = ei[e], d = ei[N_EDGES + e];
        int pos = g_rowptr[d] + atomicAdd(&g_fill[d], 1);
        g_edge[pos] = make_int2(s, __float_as_int(g_dinv[s] * g_dinv[d]));
    }
}

// ---------------- tf32 tensor-core GEMM: [n x K] @ [K x 64] -> half [n x 64] ----------------
template <int K>
__global__ void gemm64_tc(const float* __restrict__ A, const float* __restrict__ W,
                          __half* __restrict__ C, int n) {
    extern __shared__ float sm[];
    float (*As)[40] = reinterpret_cast<float(*)[40]>(sm);
    int tid = threadIdx.x, wid = tid >> 5, lane = tid & 31;
    int wm = wid >> 1, wn = wid & 1;
    int n0 = blockIdx.x * 128;

    wmma::fragment<wmma::accumulator, 16, 16, 8, float> cf[2][2];
    #pragma unroll
    for (int mm = 0; mm < 2; mm++)
        #pragma unroll
        for (int nn = 0; nn < 2; nn++)
            wmma::fill_fragment(cf[mm][nn], 0.0f);

    for (int k0 = 0; k0 < K; k0 += 32) {
        #pragma unroll
        for (int i = 0; i < 4; i++) {
            int f4 = tid + i * 256;
            int r  = f4 >> 3;
            int c4 = (f4 & 7) * 4;
            int gr = n0 + r;
            float4 v = (gr < n)
                ? *reinterpret_cast<const float4*>(A + (size_t)gr * K + k0 + c4)
                : make_float4(0.f, 0.f, 0.f, 0.f);
            As[r][c4 + 0] = wmma::__float_to_tf32(v.x);
            As[r][c4 + 1] = wmma::__float_to_tf32(v.y);
            As[r][c4 + 2] = wmma::__float_to_tf32(v.z);
            As[r][c4 + 3] = wmma::__float_to_tf32(v.w);
        }
        __syncthreads();
        #pragma unroll
        for (int ks = 0; ks < 4; ks++) {
            wmma::fragment<wmma::matrix_b, 16, 16, 8, wmma::precision::tf32, wmma::row_major> bf[2];
            #pragma unroll
            for (int nn = 0; nn < 2; nn++) {
                wmma::load_matrix_sync(bf[nn], W + (k0 + ks * 8) * 64 + wn * 32 + nn * 16, 64);
                #pragma unroll
                for (int t = 0; t < bf[nn].num_elements; t++)
                    bf[nn].x[t] = wmma::__float_to_tf32(bf[nn].x[t]);
            }
            wmma::fragment<wmma::matrix_a, 16, 16, 8, wmma::precision::tf32, wmma::row_major> af[2];
            #pragma unroll
            for (int mm = 0; mm < 2; mm++)
                wmma::load_matrix_sync(af[mm], &As[wm * 32 + mm * 16][ks * 8], 40);
            #pragma unroll
            for (int mm = 0; mm < 2; mm++)
                #pragma unroll
                for (int nn = 0; nn < 2; nn++)
                    wmma::mma_sync(cf[mm][nn], af[mm], bf[nn], cf[mm][nn]);
        }
        __syncthreads();
    }

    float* Cs = sm + wid * (32 * 36);
    #pragma unroll
    for (int mm = 0; mm < 2; mm++)
        #pragma unroll
        for (int nn = 0; nn < 2; nn++)
            wmma::store_matrix_sync(Cs + mm * 16 * 36 + nn * 16, cf[mm][nn], 36, wmma::mem_row_major);
    __syncwarp();

    int gr = n0 + wm * 32 + lane;
    if (gr < n) {
        __half2* dst = reinterpret_cast<__half2*>(C + (size_t)gr * 64 + wn * 32);
        const float* src = Cs + lane * 36;
        #pragma unroll
        for (int cc = 0; cc < 16; cc++)
            dst[cc] = __floats2half2_rn(src[cc * 2], src[cc * 2 + 1]);
    }
}

// ---------------- GEMM: [n x 64] @ [64 x 10] -> [n x 10] fp32 ----------------
__global__ void gemm_out10(const float* __restrict__ A, const float* __restrict__ W,
                           float* __restrict__ C, int n) {
    __shared__ float Ws[64][10];
    __shared__ float As[16][257];
    int tid = threadIdx.x;
    for (int i = tid; i < 640; i += 256) Ws[i / 10][i % 10] = W[i];
    int n0 = blockIdx.x * 256;
    float acc[10];
    #pragma unroll
    for (int c = 0; c < 10; c++) acc[c] = 0.f;

    for (int k0 = 0; k0 < 64; k0 += 16) {
        #pragma unroll
        for (int i = 0; i < 4; i++) {
            int flat4 = tid + i * 256;
            int node = flat4 >> 2;
            int kp = (flat4 & 3) * 4;
            int gn = n0 + node;
            float4 v = (gn < n)
                ? *reinterpret_cast<const float4*>(&A[(size_t)gn * 64 + k0 + kp])
                : make_float4(0.f, 0.f, 0.f, 0.f);
            As[kp][node] = v.x; As[kp + 1][node] = v.y;
            As[kp + 2][node] = v.z; As[kp + 3][node] = v.w;
        }
        __syncthreads();
        #pragma unroll
        for (int kk = 0; kk < 16; kk++) {
            float a = As[kk][tid];
            #pragma unroll
            for (int c = 0; c < 10; c++) acc[c] += a * Ws[k0 + kk][c];
        }
        __syncthreads();
    }
    int gn = n0 + tid;
    if (gn < n) {
        #pragma unroll
        for (int c = 0; c < 10; c++) C[(size_t)gn * 10 + c] = acc[c];
    }
}

// ---------------- propagation, 64 ch fp16, 4 edge-streams per warp ----------------
__global__ void prop64(const __half* __restrict__ Hin, float* __restrict__ Hout,
                       const float* __restrict__ bias, int n, int do_relu) {
    int gtid = blockIdx.x * blockDim.x + threadIdx.x;
    int v = gtid >> 5;
    int lane = threadIdx.x & 31;
    int wl = threadIdx.x >> 5;
    int grp = lane >> 3;     // 0..3 : edge stream
    int sub = lane & 7;      // 0..7 : 8 channels each (16B)
    __shared__ int2 s_e[8][32];
    if (v >= n) return;

    float acc[8];
    #pragma unroll
    for (int i = 0; i < 8; i++) acc[i] = 0.f;

    float dv = g_dinv[v];
    if (grp == 0) {
        float selfn = dv * dv;
        uint4 q = *(reinterpret_cast<const uint4*>(Hin + (size_t)v * 64) + sub);
        float2 f0 = __half22float2(*reinterpret_cast<__half2*>(&q.x));
        float2 f1 = __half22float2(*reinterpret_cast<__half2*>(&q.y));
        float2 f2 = __half22float2(*reinterpret_cast<__half2*>(&q.z));
        float2 f3 = __half22float2(*reinterpret_cast<__half2*>(&q.w));
        acc[0] = selfn * f0.x; acc[1] = selfn * f0.y;
        acc[2] = selfn * f1.x; acc[3] = selfn * f1.y;
        acc[4] = selfn * f2.x; acc[5] = selfn * f2.y;
        acc[6] = selfn * f3.x; acc[7] = selfn * f3.y;
    }

    int e0 = g_rowptr[v], e1 = g_rowptr[v + 1];
    for (int base = e0; base < e1; base += 32) {
        int ne = min(32, e1 - base);
        if (lane < ne) s_e[wl][lane] = g_edge[base + lane];
        __syncwarp();
        #pragma unroll 2
        for (int j = grp; j < ne; j += 4) {
            int2 e = s_e[wl][j];
            float nm = __int_as_float(e.y);
            uint4 q = *(reinterpret_cast<const uint4*>(Hin + (size_t)e.x * 64) + sub);
            float2 f0 = __half22float2(*reinterpret_cast<__half2*>(&q.x));
            float2 f1 = __half22float2(*reinterpret_cast<__half2*>(&q.y));
            float2 f2 = __half22float2(*reinterpret_cast<__half2*>(&q.z));
            float2 f3 = __half22float2(*reinterpret_cast<__half2*>(&q.w));
            acc[0] += nm * f0.x; acc[1] += nm * f0.y;
            acc[2] += nm * f1.x; acc[3] += nm * f1.y;
            acc[4] += nm * f2.x; acc[5] += nm * f2.y;
            acc[6] += nm * f3.x; acc[7] += nm * f3.y;
        }
        __syncwarp();
    }

    // combine the 4 edge streams
    #pragma unroll
    for (int i = 0; i < 8; i++) {
        acc[i] += __shfl_down_sync(0xffffffffu, acc[i], 16);
        acc[i] += __shfl_down_sync(0xffffffffu, acc[i], 8);
    }
    if (grp == 0) {
        const float4* b4 = reinterpret_cast<const float4*>(bias);
        float4 ba = b4[sub * 2], bb = b4[sub * 2 + 1];
        float4 o0 = make_float4(acc[0] + ba.x, acc[1] + ba.y, acc[2] + ba.z, acc[3] + ba.w);
        float4 o1 = make_float4(acc[4] + bb.x, acc[5] + bb.y, acc[6] + bb.z, acc[7] + bb.w);
        if (do_relu) {
            o0.x = fmaxf(o0.x, 0.f); o0.y = fmaxf(o0.y, 0.f);
            o0.z = fmaxf(o0.z, 0.f); o0.w = fmaxf(o0.w, 0.f);
            o1.x = fmaxf(o1.x, 0.f); o1.y = fmaxf(o1.y, 0.f);
            o1.z = fmaxf(o1.z, 0.f); o1.w = fmaxf(o1.w, 0.f);
        }
        float4* dst = reinterpret_cast<float4*>(Hout + (size_t)v * 64) + sub * 2;
        dst[0] = o0; dst[1] = o1;
    }
}

// ---------------- propagation 10ch + fused pool, 6 edge-streams per warp ----------------
__global__ void prop10_pool(const float* __restrict__ Hin, const float* __restrict__ bias,
                            const int* __restrict__ batch, int n) {
    int gtid = blockIdx.x * blockDim.x + threadIdx.x;
    int v = gtid >> 5;
    int lane = threadIdx.x & 31;
    int wl = threadIdx.x >> 5;
    int grp = lane / 5;            // 0..5 for lane<30, 6 for 30/31
    int sub = lane - grp * 5;      // 0..4 : channels {2sub, 2sub+1}
    bool act = lane < 30;
    __shared__ int2 s_e[8][32];
    if (v >= n) return;

    float dv = g_dinv[v];
    float2 acc = make_float2(0.f, 0.f);
    if (lane < 5) {
        float selfn = dv * dv;
        float2 hv = *(reinterpret_cast<const float2*>(Hin + (size_t)v * 10) + sub);
        acc.x = selfn * hv.x; acc.y = selfn * hv.y;
    }

    int e0 = g_rowptr[v], e1 = g_rowptr[v + 1];
    for (int base = e0; base < e1; base += 32) {
        int ne = min(32, e1 - base);
        if (lane < ne) s_e[wl][lane] = g_edge[base + lane];
        __syncwarp();
        if (act) {
            for (int j = grp; j < ne; j += 6) {
                int2 e = s_e[wl][j];
                float nm = __int_as_float(e.y);
                float2 hv = *(reinterpret_cast<const float2*>(Hin + (size_t)e.x * 10) + sub);
                acc.x += nm * hv.x;
                acc.y += nm * hv.y;
            }
        }
        __syncwarp();
    }

    // fold 6 streams into lanes 0..4 (read originals, accumulate separately)
    float sx = acc.x, sy = acc.y;
    #pragma unroll
    for (int off = 5; off < 30; off += 5) {
        float tx = __shfl_sync(0xffffffffu, acc.x, lane + off);
        float ty = __shfl_sync(0xffffffffu, acc.y, lane + off);
        if (lane < 5) { sx += tx; sy += ty; }
    }
    int g = batch[v];
    if (lane < 5) {
        atomicAdd(&g_pool[g * 10 + 2 * sub],     sx + bias[2 * sub]);
        atomicAdd(&g_pool[g * 10 + 2 * sub + 1], sy + bias[2 * sub + 1]);
    }
    if (lane == 30) atomicAdd(&g_pcnt[g], 1.f);
}

// ---------------- final mean + log_softmax ----------------
__global__ void final_kernel(float* __restrict__ out) {
    int g = threadIdx.x;
    if (g >= NUM_GRAPHS) return;
    float inv = 1.f / fmaxf(g_pcnt[g], 1.f);
    float v[NUM_CLASSES];
    float m = -1e30f;
    #pragma unroll
    for (int c = 0; c < NUM_CLASSES; c++) {
        v[c] = g_pool[g * 10 + c] * inv;
        m = fmaxf(m, v[c]);
    }
    float ssum = 0.f;
    #pragma unroll
    for (int c = 0; c < NUM_CLASSES; c++) ssum += expf(v[c] - m);
    float lse = m + logf(ssum);
    #pragma unroll
    for (int c = 0; c < NUM_CLASSES; c++) out[g * 10 + c] = v[c] - lse;
}

// ---------------- launch ----------------
extern "C" void kernel_launch(void* const* d_in, const int* in_sizes, int n_in,
                              void* d_out, int out_size) {
    const float* x   = (const float*)d_in[0];
    const int*   ei  = (const int*)d_in[1];
    const int*   bat = (const int*)d_in[2];
    const float* W1  = (const float*)d_in[3];
    const float* b1  = (const float*)d_in[4];
    const float* W2  = (const float*)d_in[5];
    const float* b2  = (const float*)d_in[6];
    const float* W3  = (const float*)d_in[7];
    const float* b3  = (const float*)d_in[8];
    float* out = (float*)d_out;

    __half* th = nullptr; float* h = nullptr; float* t10 = nullptr;
    void *p_cnt, *p_fill, *p_pool, *p_pcnt;
    cudaGetSymbolAddress((void**)&th, g_th);
    cudaGetSymbolAddress((void**)&h, g_h);
    cudaGetSymbolAddress((void**)&t10, g_t10);
    cudaGetSymbolAddress(&p_cnt, g_cnt);
    cudaGetSymbolAddress(&p_fill, g_fill);
    cudaGetSymbolAddress(&p_pool, g_pool);
    cudaGetSymbolAddress(&p_pcnt, g_pcnt);

    static cudaStream_t s2 = nullptr;
    static cudaEvent_t evFork = nullptr, evJoin = nullptr;
    if (s2 == nullptr) {
        cudaStreamCreateWithFlags(&s2, cudaStreamNonBlocking);
        cudaEventCreateWithFlags(&evFork, cudaEventDisableTiming);
        cudaEventCreateWithFlags(&evJoin, cudaEventDisableTiming);
    }

    const int TB = 256;
    int nblk  = (N_NODES + TB - 1) / TB;
    int c4blk = (N_EDGES / 4 + TB - 1) / TB;
    int s2blk = (N_EDGES / 2 + TB - 1) / TB;
    int wblk  = (N_NODES * 32 + TB - 1) / TB;
    int gblk  = (N_NODES + 127) / 128;
    const size_t GSM = 8 * 32 * 36 * sizeof(float);

    cudaMemsetAsync(p_pool, 0, NUM_GRAPHS * NUM_CLASSES * sizeof(float), 0);
    cudaMemsetAsync(p_pcnt, 0, NUM_GRAPHS * sizeof(float), 0);

    // ---- fork: CSR preprocessing on s2, GEMM-1 on main ----
    cudaEventRecord(evFork, 0);
    cudaStreamWaitEvent(s2, evFork, 0);

    cudaMemsetAsync(p_cnt,  0, N_NODES * sizeof(int), s2);
    cudaMemsetAsync(p_fill, 0, N_NODES * sizeof(int), s2);
    count_kernel<<<c4blk, TB, 0, s2>>>(ei);
    blocksum_dinv<<<SCAN_NBLK, SCAN_BS, 0, s2>>>();
    scan_partials<<<1, 128, 0, s2>>>();
    write_rowptr<<<SCAN_NBLK, SCAN_BS, 0, s2>>>();
    scatter_kernel<<<s2blk, TB, 0, s2>>>(ei);
    cudaEventRecord(evJoin, s2);

    gemm64_tc<IN_CH><<<gblk, TB, GSM>>>(x, W1, th, N_NODES);

    cudaStreamWaitEvent(0, evJoin, 0);

    prop64<<<wblk, TB>>>(th, h, b1, N_NODES, 1);
    gemm64_tc<HID><<<gblk, TB, GSM>>>(h, W2, th, N_NODES);
    prop64<<<wblk, TB>>>(th, h, b2, N_NODES, 1);
    gemm_out10<<<nblk, TB>>>(h, W3, t10, N_NODES);
    prop10_pool<<<wblk, TB>>>(t10, b3, bat, N_NODES);

    final_kernel<<<1, 64>>>(out);
}

// round 5
// speedup vs baseline: 1.0149x; 1.0149x over previous
#include <cuda_runtime.h>
#include <cuda_fp16.h>
#include <math.h>
#include <mma.h>

using namespace nvcuda;

#define N_NODES   100000
#define N_EDGES   1600000
#define NUM_GRAPHS 64
#define IN_CH     128
#define HID       64
#define NUM_CLASSES 10

#define SCAN_BS   256
#define SCAN_IT   4
#define SCAN_CHUNK (SCAN_BS * SCAN_IT)
#define SCAN_NBLK ((N_NODES + SCAN_CHUNK - 1) / SCAN_CHUNK)  // 98
#define LB_FLAG   (1 << 30)

// ---------------- scratch ----------------
__device__ int   g_cnt[N_NODES];            // zero-init; scatter restores to zero
__device__ float g_dinv[N_NODES];
__device__ int   g_rowptr[N_NODES + 1];
__device__ int2  g_edge[N_EDGES];
__device__ int   g_look[SCAN_NBLK];         // decoupled-lookback words
__device__ __align__(128) __half g_th[(size_t)N_NODES * HID];  // GEMM outputs
__device__ __align__(128) __half g_hh[(size_t)N_NODES * HID];  // prop outputs
__device__ __align__(128) float  g_t10[(size_t)N_NODES * NUM_CLASSES];
__device__ float g_pool[NUM_GRAPHS * NUM_CLASSES];  // zero-init; final restores
__device__ float g_pcnt[NUM_GRAPHS];

// ---------------- degree count ----------------
__global__ void count_kernel(const int* __restrict__ ei) {
    int e = blockIdx.x * blockDim.x + threadIdx.x;
    if (e < N_EDGES) atomicAdd(&g_cnt[ei[N_EDGES + e]], 1);
}

// ---------------- fused dinv + exclusive scan (decoupled lookback) ----------------
__global__ void build_rowptr() {
    int b = blockIdx.x, t = threadIdx.x;
    int lane = t & 31, warp = t >> 5;
    int i0 = b * SCAN_CHUNK + t * SCAN_IT;
    int v[SCAN_IT]; int s = 0;
    #pragma unroll
    for (int i = 0; i < SCAN_IT; i++) {
        int idx = i0 + i;
        int c = 0;
        if (idx < N_NODES) {
            c = g_cnt[idx];
            g_dinv[idx] = rsqrtf((float)(c + 1));
        }
        s += c; v[i] = s;
    }
    // warp inclusive scan of thread sums
    int x = s;
    #pragma unroll
    for (int off = 1; off < 32; off <<= 1) {
        int y = __shfl_up_sync(0xffffffffu, x, off);
        if (lane >= off) x += y;
    }
    __shared__ int ws[8];
    __shared__ int s_base;
    if (lane == 31) ws[warp] = x;
    if (t == 0) s_base = 0;

    // poll predecessors while this block's smem scan settles
    int contrib = 0;
    if (t < b) {
        volatile int* lk = (volatile int*)&g_look[t];
        int val = *lk;
        while (val < LB_FLAG) { __nanosleep(64); val = *lk; }
        contrib = val - LB_FLAG;
    }
    __syncthreads();
    if (warp == 0 && lane < 8) {
        int w = ws[lane];
        int iw = w;
        #pragma unroll
        for (int off = 1; off < 8; off <<= 1) {
            int y = __shfl_up_sync(0xffu, iw, off);
            if (lane >= off) iw += y;
        }
        ws[lane] = iw - w;                       // exclusive warp base
        if (lane == 7) atomicExch(&g_look[b], iw | LB_FLAG);  // publish block total
    }
    #pragma unroll
    for (int off = 16; off; off >>= 1) contrib += __shfl_down_sync(0xffffffffu, contrib, off);
    if (lane == 0 && contrib) atomicAdd(&s_base, contrib);
    __syncthreads();

    int excl = s_base + ws[warp] + (x - s);
    #pragma unroll
    for (int i = 0; i < SCAN_IT; i++) {
        int idx = i0 + i;
        if (idx < N_NODES) g_rowptr[idx + 1] = excl + v[i];
    }
    if (b == 0 && t == 0) g_rowptr[0] = 0;
}

// ---------------- CSR scatter (g_cnt as down-cursor; restores it to zero) ----------------
__global__ void scatter_kernel(const int* __restrict__ ei) {
    int e = blockIdx.x * blockDim.x + threadIdx.x;
    if (e < N_EDGES) {
        int s = ei[e];
        int d = ei[N_EDGES + e];
        int pos = g_rowptr[d] + atomicSub(&g_cnt[d], 1) - 1;
        g_edge[pos] = make_int2(s, __float_as_int(g_dinv[s] * g_dinv[d]));
    }
}

// ---------------- tf32 tensor-core GEMM: [n x K] @ [K x 64] -> half [n x 64] ----------------
template <int K, typename TA>
__global__ void gemm64_tc(const TA* __restrict__ A, const float* __restrict__ W,
                          __half* __restrict__ C, int n) {
    extern __shared__ float sm[];
    float (*As)[40] = reinterpret_cast<float(*)[40]>(sm);
    int tid = threadIdx.x, wid = tid >> 5, lane = tid & 31;
    int wm = wid >> 1, wn = wid & 1;
    int n0 = blockIdx.x * 128;

    wmma::fragment<wmma::accumulator, 16, 16, 8, float> cf[2][2];
    #pragma unroll
    for (int mm = 0; mm < 2; mm++)
        #pragma unroll
        for (int nn = 0; nn < 2; nn++)
            wmma::fill_fragment(cf[mm][nn], 0.0f);

    for (int k0 = 0; k0 < K; k0 += 32) {
        if constexpr (sizeof(TA) == 4) {
            #pragma unroll
            for (int i = 0; i < 4; i++) {
                int f4 = tid + i * 256;
                int r  = f4 >> 3;
                int c4 = (f4 & 7) * 4;
                int gr = n0 + r;
                float4 v = (gr < n)
                    ? *reinterpret_cast<const float4*>((const float*)A + (size_t)gr * K + k0 + c4)
                    : make_float4(0.f, 0.f, 0.f, 0.f);
                As[r][c4 + 0] = wmma::__float_to_tf32(v.x);
                As[r][c4 + 1] = wmma::__float_to_tf32(v.y);
                As[r][c4 + 2] = wmma::__float_to_tf32(v.z);
                As[r][c4 + 3] = wmma::__float_to_tf32(v.w);
            }
        } else {
            #pragma unroll
            for (int i = 0; i < 2; i++) {
                int u = tid + i * 256;         // 512 units of 8 halves
                int r = u >> 2;
                int c8 = (u & 3) * 8;
                int gr = n0 + r;
                uint4 q = (gr < n)
                    ? *reinterpret_cast<const uint4*>((const __half*)A + (size_t)gr * K + k0 + c8)
                    : make_uint4(0u, 0u, 0u, 0u);
                float2 f0 = __half22float2(*reinterpret_cast<__half2*>(&q.x));
                float2 f1 = __half22float2(*reinterpret_cast<__half2*>(&q.y));
                float2 f2 = __half22float2(*reinterpret_cast<__half2*>(&q.z));
                float2 f3 = __half22float2(*reinterpret_cast<__half2*>(&q.w));
                As[r][c8 + 0] = wmma::__float_to_tf32(f0.x);
                As[r][c8 + 1] = wmma::__float_to_tf32(f0.y);
                As[r][c8 + 2] = wmma::__float_to_tf32(f1.x);
                As[r][c8 + 3] = wmma::__float_to_tf32(f1.y);
                As[r][c8 + 4] = wmma::__float_to_tf32(f2.x);
                As[r][c8 + 5] = wmma::__float_to_tf32(f2.y);
                As[r][c8 + 6] = wmma::__float_to_tf32(f3.x);
                As[r][c8 + 7] = wmma::__float_to_tf32(f3.y);
            }
        }
        __syncthreads();
        #pragma unroll
        for (int ks = 0; ks < 4; ks++) {
            wmma::fragment<wmma::matrix_b, 16, 16, 8, wmma::precision::tf32, wmma::row_major> bf[2];
            #pragma unroll
            for (int nn = 0; nn < 2; nn++) {
                wmma::load_matrix_sync(bf[nn], W + (k0 + ks * 8) * 64 + wn * 32 + nn * 16, 64);
                #pragma unroll
                for (int t = 0; t < bf[nn].num_elements; t++)
                    bf[nn].x[t] = wmma::__float_to_tf32(bf[nn].x[t]);
            }
            wmma::fragment<wmma::matrix_a, 16, 16, 8, wmma::precision::tf32, wmma::row_major> af[2];
            #pragma unroll
            for (int mm = 0; mm < 2; mm++)
                wmma::load_matrix_sync(af[mm], &As[wm * 32 + mm * 16][ks * 8], 40);
            #pragma unroll
            for (int mm = 0; mm < 2; mm++)
                #pragma unroll
                for (int nn = 0; nn < 2; nn++)
                    wmma::mma_sync(cf[mm][nn], af[mm], bf[nn], cf[mm][nn]);
        }
        __syncthreads();
    }

    float* Cs = sm + wid * (32 * 36);
    #pragma unroll
    for (int mm = 0; mm < 2; mm++)
        #pragma unroll
        for (int nn = 0; nn < 2; nn++)
            wmma::store_matrix_sync(Cs + mm * 16 * 36 + nn * 16, cf[mm][nn], 36, wmma::mem_row_major);
    __syncwarp();

    int gr = n0 + wm * 32 + lane;
    if (gr < n) {
        __half2* dst = reinterpret_cast<__half2*>(C + (size_t)gr * 64 + wn * 32);
        const float* src = Cs + lane * 36;
        #pragma unroll
        for (int cc = 0; cc < 16; cc++)
            dst[cc] = __floats2half2_rn(src[cc * 2], src[cc * 2 + 1]);
    }
}

// ---------------- GEMM: half [n x 64] @ [64 x 10] -> fp32 [n x 10] ----------------
__global__ void gemm_out10(const __half* __restrict__ A, const float* __restrict__ W,
                           float* __restrict__ C, int n) {
    __shared__ float Ws[64][10];
    __shared__ float As[16][257];
    int tid = threadIdx.x;
    for (int i = tid; i < 640; i += 256) Ws[i / 10][i % 10] = W[i];
    int n0 = blockIdx.x * 256;
    float acc[10];
    #pragma unroll
    for (int c = 0; c < 10; c++) acc[c] = 0.f;

    for (int k0 = 0; k0 < 64; k0 += 16) {
        #pragma unroll
        for (int i = 0; i < 2; i++) {
            int u = tid + i * 256;          // 512 units of 8 halves
            int node = u >> 1;
            int c8 = (u & 1) * 8;
            int gn = n0 + node;
            uint4 q = (gn < n)
                ? *reinterpret_cast<const uint4*>(A + (size_t)gn * 64 + k0 + c8)
                : make_uint4(0u, 0u, 0u, 0u);
            float2 f0 = __half22float2(*reinterpret_cast<__half2*>(&q.x));
            float2 f1 = __half22float2(*reinterpret_cast<__half2*>(&q.y));
            float2 f2 = __half22float2(*reinterpret_cast<__half2*>(&q.z));
            float2 f3 = __half22float2(*reinterpret_cast<__half2*>(&q.w));
            As[c8 + 0][node] = f0.x; As[c8 + 1][node] = f0.y;
            As[c8 + 2][node] = f1.x; As[c8 + 3][node] = f1.y;
            As[c8 + 4][node] = f2.x; As[c8 + 5][node] = f2.y;
            As[c8 + 6][node] = f3.x; As[c8 + 7][node] = f3.y;
        }
        __syncthreads();
        #pragma unroll
        for (int kk = 0; kk < 16; kk++) {
            float a = As[kk][tid];
            #pragma unroll
            for (int c = 0; c < 10; c++) acc[c] += a * Ws[k0 + kk][c];
        }
        __syncthreads();
    }
    int gn = n0 + tid;
    if (gn < n) {
        #pragma unroll
        for (int c = 0; c < 10; c++) C[(size_t)gn * 10 + c] = acc[c];
    }
}

// ---------------- propagation, 64 ch fp16 -> fp16: warp per node (R3 form) ----------------
__global__ void prop64(const __half* __restrict__ Hin, __half* __restrict__ Hout,
                       const float* __restrict__ bias, int n, int do_relu) {
    int gtid = blockIdx.x * blockDim.x + threadIdx.x;
    int v = gtid >> 5;
    int lane = threadIdx.x & 31;
    int wl = threadIdx.x >> 5;
    __shared__ int2 s_e[8][32];
    if (v >= n) return;

    float dv = g_dinv[v];
    float selfn = dv * dv;
    float2 xv = __half22float2(reinterpret_cast<const __half2*>(Hin + (size_t)v * 64)[lane]);
    float2 acc = make_float2(selfn * xv.x, selfn * xv.y);

    int e0 = g_rowptr[v], e1 = g_rowptr[v + 1];
    for (int base = e0; base < e1; base += 32) {
        int ne = min(32, e1 - base);
        if (lane < ne) s_e[wl][lane] = g_edge[base + lane];
        __syncwarp();
        #pragma unroll 4
        for (int j = 0; j < ne; j++) {
            int2 e = s_e[wl][j];
            float nm = __int_as_float(e.y);
            float2 hh = __half22float2(
                reinterpret_cast<const __half2*>(Hin + (size_t)e.x * 64)[lane]);
            acc.x += nm * hh.x;
            acc.y += nm * hh.y;
        }
        __syncwarp();
    }
    float2 b = reinterpret_cast<const float2*>(bias)[lane];
    acc.x += b.x; acc.y += b.y;
    if (do_relu) {
        acc.x = fmaxf(acc.x, 0.f);
        acc.y = fmaxf(acc.y, 0.f);
    }
    reinterpret_cast<__half2*>(Hout + (size_t)v * 64)[lane] = __floats2half2_rn(acc.x, acc.y);
}

// ---------------- propagation 10ch + fused mean-pool (R3 form) ----------------
__global__ void prop10_pool(const float* __restrict__ Hin, const float* __restrict__ bias,
                            const int* __restrict__ batch, int n) {
    int gtid = blockIdx.x * blockDim.x + threadIdx.x;
    int v = gtid >> 5;
    int lane = threadIdx.x & 31;
    int wl = threadIdx.x >> 5;
    __shared__ int2 s_e[8][32];
    if (v >= n) return;

    float dv = g_dinv[v];
    float selfn = dv * dv;
    float acc = 0.f;
    if (lane < NUM_CLASSES) acc = selfn * Hin[(size_t)v * 10 + lane];

    int e0 = g_rowptr[v], e1 = g_rowptr[v + 1];
    for (int base = e0; base < e1; base += 32) {
        int ne = min(32, e1 - base);
        if (lane < ne) s_e[wl][lane] = g_edge[base + lane];
        __syncwarp();
        for (int j = 0; j < ne; j++) {
            int2 e = s_e[wl][j];
            float nm = __int_as_float(e.y);
            if (lane < NUM_CLASSES)
                acc += nm * Hin[(size_t)e.x * 10 + lane];
        }
        __syncwarp();
    }
    int g = batch[v];
    if (lane < NUM_CLASSES)
        atomicAdd(&g_pool[g * 10 + lane], acc + bias[lane]);
    if (lane == NUM_CLASSES)
        atomicAdd(&g_pcnt[g], 1.f);
}

// ---------------- final mean + log_softmax (self-restoring: zeroes pool) ----------------
__global__ void final_kernel(float* __restrict__ out) {
    int g = threadIdx.x;
    if (g >= NUM_GRAPHS) return;
    float inv = 1.f / fmaxf(g_pcnt[g], 1.f);
    float v[NUM_CLASSES];
    float m = -1e30f;
    #pragma unroll
    for (int c = 0; c < NUM_CLASSES; c++) {
        v[c] = g_pool[g * 10 + c] * inv;
        m = fmaxf(m, v[c]);
    }
    float ssum = 0.f;
    #pragma unroll
    for (int c = 0; c < NUM_CLASSES; c++) ssum += expf(v[c] - m);
    float lse = m + logf(ssum);
    #pragma unroll
    for (int c = 0; c < NUM_CLASSES; c++) {
        out[g * 10 + c] = v[c] - lse;
        g_pool[g * 10 + c] = 0.f;
    }
    g_pcnt[g] = 0.f;
}

// ---------------- launch ----------------
extern "C" void kernel_launch(void* const* d_in, const int* in_sizes, int n_in,
                              void* d_out, int out_size) {
    const float* x   = (const float*)d_in[0];
    const int*   ei  = (const int*)d_in[1];
    const int*   bat = (const int*)d_in[2];
    const float* W1  = (const float*)d_in[3];
    const float* b1  = (const float*)d_in[4];
    const float* W2  = (const float*)d_in[5];
    const float* b2  = (const float*)d_in[6];
    const float* W3  = (const float*)d_in[7];
    const float* b3  = (const float*)d_in[8];
    float* out = (float*)d_out;

    __half* th = nullptr; __half* hh = nullptr; float* t10 = nullptr;
    void* p_look = nullptr;
    cudaGetSymbolAddress((void**)&th, g_th);
    cudaGetSymbolAddress((void**)&hh, g_hh);
    cudaGetSymbolAddress((void**)&t10, g_t10);
    cudaGetSymbolAddress(&p_look, g_look);

    static cudaStream_t s2 = nullptr;
    static cudaEvent_t evFork = nullptr, evJoin = nullptr;
    if (s2 == nullptr) {
        cudaStreamCreateWithFlags(&s2, cudaStreamNonBlocking);
        cudaEventCreateWithFlags(&evFork, cudaEventDisableTiming);
        cudaEventCreateWithFlags(&evJoin, cudaEventDisableTiming);
    }

    const int TB = 256;
    int nblk  = (N_NODES + TB - 1) / TB;
    int eblk  = (N_EDGES + TB - 1) / TB;
    int wblk  = (N_NODES * 32 + TB - 1) / TB;
    int gblk  = (N_NODES + 127) / 128;
    const size_t GSM = 8 * 32 * 36 * sizeof(float);

    // ---- fork: CSR preprocessing on s2, GEMM-1 on main ----
    cudaEventRecord(evFork, 0);
    cudaStreamWaitEvent(s2, evFork, 0);

    cudaMemsetAsync(p_look, 0, SCAN_NBLK * sizeof(int), s2);
    count_kernel<<<eblk, TB, 0, s2>>>(ei);
    build_rowptr<<<SCAN_NBLK, SCAN_BS, 0, s2>>>();
    scatter_kernel<<<eblk, TB, 0, s2>>>(ei);
    cudaEventRecord(evJoin, s2);

    gemm64_tc<IN_CH, float><<<gblk, TB, GSM>>>(x, W1, th, N_NODES);

    cudaStreamWaitEvent(0, evJoin, 0);

    prop64<<<wblk, TB>>>(th, hh, b1, N_NODES, 1);
    gemm64_tc<HID, __half><<<gblk, TB, GSM>>>(hh, W2, th, N_NODES);
    prop64<<<wblk, TB>>>(th, hh, b2, N_NODES, 1);
    gemm_out10<<<nblk, TB>>>(hh, W3, t10, N_NODES);
    prop10_pool<<<wblk, TB>>>(t10, b3, bat, N_NODES);

    final_kernel<<<1, 64>>>(out);
}

// round 6
// speedup vs baseline: 1.0621x; 1.0466x over previous
#include <cuda_runtime.h>
#include <cuda_fp16.h>
#include <math.h>
#include <mma.h>

using namespace nvcuda;

#define N_NODES   100000
#define N_EDGES   1600000
#define NUM_GRAPHS 64
#define IN_CH     128
#define HID       64
#define NUM_CLASSES 10

#define SCAN_BS   256
#define SCAN_IT   4
#define SCAN_CHUNK (SCAN_BS * SCAN_IT)
#define SCAN_NBLK ((N_NODES + SCAN_CHUNK - 1) / SCAN_CHUNK)  // 98
#define LB_FLAG   (1 << 30)

// ---------------- scratch ----------------
__device__ int   g_cnt[N_NODES];            // zero-init; scatter restores to zero
__device__ float g_dinv[N_NODES];
__device__ int   g_rowptr[N_NODES + 1];
__device__ int2  g_edge[N_EDGES];
__device__ int   g_look[SCAN_NBLK];
__device__ __align__(128) __half g_th[(size_t)N_NODES * HID];  // GEMM outputs
__device__ __align__(128) __half g_hh[(size_t)N_NODES * HID];  // prop outputs
__device__ __align__(128) float  g_t10[(size_t)N_NODES * NUM_CLASSES];
__device__ float g_pool[NUM_GRAPHS * NUM_CLASSES];  // zero-init; final restores
__device__ float g_pcnt[NUM_GRAPHS];

// ---------------- degree count ----------------
__global__ void count_kernel(const int* __restrict__ ei) {
    int e = blockIdx.x * blockDim.x + threadIdx.x;
    if (e < N_EDGES) atomicAdd(&g_cnt[ei[N_EDGES + e]], 1);
}

// ---------------- fused dinv + exclusive scan (decoupled lookback) ----------------
__global__ void build_rowptr() {
    int b = blockIdx.x, t = threadIdx.x;
    int lane = t & 31, warp = t >> 5;
    int i0 = b * SCAN_CHUNK + t * SCAN_IT;
    int v[SCAN_IT]; int s = 0;
    #pragma unroll
    for (int i = 0; i < SCAN_IT; i++) {
        int idx = i0 + i;
        int c = 0;
        if (idx < N_NODES) {
            c = g_cnt[idx];
            g_dinv[idx] = rsqrtf((float)(c + 1));
        }
        s += c; v[i] = s;
    }
    int x = s;
    #pragma unroll
    for (int off = 1; off < 32; off <<= 1) {
        int y = __shfl_up_sync(0xffffffffu, x, off);
        if (lane >= off) x += y;
    }
    __shared__ int ws[8];
    __shared__ int s_base;
    if (lane == 31) ws[warp] = x;
    if (t == 0) s_base = 0;

    int contrib = 0;
    if (t < b) {
        volatile int* lk = (volatile int*)&g_look[t];
        int val = *lk;
        while (val < LB_FLAG) { __nanosleep(64); val = *lk; }
        contrib = val - LB_FLAG;
    }
    __syncthreads();
    if (warp == 0 && lane < 8) {
        int w = ws[lane];
        int iw = w;
        #pragma unroll
        for (int off = 1; off < 8; off <<= 1) {
            int y = __shfl_up_sync(0xffu, iw, off);
            if (lane >= off) iw += y;
        }
        ws[lane] = iw - w;
        if (lane == 7) atomicExch(&g_look[b], iw | LB_FLAG);
    }
    #pragma unroll
    for (int off = 16; off; off >>= 1) contrib += __shfl_down_sync(0xffffffffu, contrib, off);
    if (lane == 0 && contrib) atomicAdd(&s_base, contrib);
    __syncthreads();

    int excl = s_base + ws[warp] + (x - s);
    #pragma unroll
    for (int i = 0; i < SCAN_IT; i++) {
        int idx = i0 + i;
        if (idx < N_NODES) g_rowptr[idx + 1] = excl + v[i];
    }
    if (b == 0 && t == 0) g_rowptr[0] = 0;
}

// ---------------- CSR scatter ----------------
__global__ void scatter_kernel(const int* __restrict__ ei) {
    int e = blockIdx.x * blockDim.x + threadIdx.x;
    if (e < N_EDGES) {
        int s = ei[e];
        int d = ei[N_EDGES + e];
        int pos = g_rowptr[d] + atomicSub(&g_cnt[d], 1) - 1;
        g_edge[pos] = make_int2(s, __float_as_int(g_dinv[s] * g_dinv[d]));
    }
}

// ---------------- fp16 HMMA GEMM: [n x K] @ [K x 64] -> half [n x 64] ----------------
// block 256 thr = 8 warps (4 Mwarps x 2 Nwarps), tile 128x64, warp tile 32x32.
// A staged to half smem (converted inline), W preloaded to half smem once.
template <int K, typename TA>
__global__ void gemm64_hmma(const TA* __restrict__ A, const float* __restrict__ W,
                            __half* __restrict__ C, int n) {
    extern __shared__ char smraw[];
    __half (*Ash)[40] = reinterpret_cast<__half(*)[40]>(smraw);                 // 128 x (32+8)
    __half (*Wsh)[72] = reinterpret_cast<__half(*)[72]>(smraw + 128 * 40 * 2);  // K x (64+8)
    float* Cs = reinterpret_cast<float*>(smraw);                                 // epilogue reuse
    int tid = threadIdx.x, wid = tid >> 5, lane = tid & 31;
    int wm = wid >> 1, wn = wid & 1;
    int n0 = blockIdx.x * 128;

    // preload W (K x 64 fp32 -> half smem)
    for (int i = tid; i < K * 16; i += 256) {       // K*64/4 float4 units
        float4 w = reinterpret_cast<const float4*>(W)[i];
        int k = (i * 4) >> 6, c = (i * 4) & 63;
        Wsh[k][c + 0] = __float2half(w.x);
        Wsh[k][c + 1] = __float2half(w.y);
        Wsh[k][c + 2] = __float2half(w.z);
        Wsh[k][c + 3] = __float2half(w.w);
    }

    wmma::fragment<wmma::accumulator, 16, 16, 16, float> cf[2][2];
    #pragma unroll
    for (int mm = 0; mm < 2; mm++)
        #pragma unroll
        for (int nn = 0; nn < 2; nn++)
            wmma::fill_fragment(cf[mm][nn], 0.0f);

    for (int k0 = 0; k0 < K; k0 += 32) {
        if constexpr (sizeof(TA) == 4) {
            // fp32 A: 128 rows x 32 cols = 1024 float4 units, convert to half
            #pragma unroll
            for (int i = 0; i < 4; i++) {
                int f4 = tid + i * 256;
                int r  = f4 >> 3;
                int c4 = (f4 & 7) * 4;
                int gr = n0 + r;
                float4 v = (gr < n)
                    ? *reinterpret_cast<const float4*>((const float*)A + (size_t)gr * K + k0 + c4)
                    : make_float4(0.f, 0.f, 0.f, 0.f);
                __half2* dst = reinterpret_cast<__half2*>(&Ash[r][c4]);
                dst[0] = __floats2half2_rn(v.x, v.y);
                dst[1] = __floats2half2_rn(v.z, v.w);
            }
        } else {
            // fp16 A: 128 rows x 32 cols = 512 uint4 units (8 halves each)
            #pragma unroll
            for (int i = 0; i < 2; i++) {
                int u = tid + i * 256;
                int r = u >> 2;
                int c8 = (u & 3) * 8;
                int gr = n0 + r;
                uint4 q = (gr < n)
                    ? *reinterpret_cast<const uint4*>((const __half*)A + (size_t)gr * K + k0 + c8)
                    : make_uint4(0u, 0u, 0u, 0u);
                *reinterpret_cast<uint4*>(&Ash[r][c8]) = q;
            }
        }
        __syncthreads();
        #pragma unroll
        for (int ks = 0; ks < 2; ks++) {
            wmma::fragment<wmma::matrix_a, 16, 16, 16, __half, wmma::row_major> af[2];
            wmma::fragment<wmma::matrix_b, 16, 16, 16, __half, wmma::row_major> bf[2];
            #pragma unroll
            for (int mm = 0; mm < 2; mm++)
                wmma::load_matrix_sync(af[mm], &Ash[wm * 32 + mm * 16][ks * 16], 40);
            #pragma unroll
            for (int nn = 0; nn < 2; nn++)
                wmma::load_matrix_sync(bf[nn], &Wsh[k0 + ks * 16][wn * 32 + nn * 16], 72);
            #pragma unroll
            for (int mm = 0; mm < 2; mm++)
                #pragma unroll
                for (int nn = 0; nn < 2; nn++)
                    wmma::mma_sync(cf[mm][nn], af[mm], bf[nn], cf[mm][nn]);
        }
        __syncthreads();
    }

    // epilogue: stage accum in smem (reuses A/W space), convert to half
    float* Cw = Cs + wid * (32 * 36);
    #pragma unroll
    for (int mm = 0; mm < 2; mm++)
        #pragma unroll
        for (int nn = 0; nn < 2; nn++)
            wmma::store_matrix_sync(Cw + mm * 16 * 36 + nn * 16, cf[mm][nn], 36, wmma::mem_row_major);
    __syncwarp();

    int gr = n0 + wm * 32 + lane;
    if (gr < n) {
        __half2* dst = reinterpret_cast<__half2*>(C + (size_t)gr * 64 + wn * 32);
        const float* src = Cw + lane * 36;
        #pragma unroll
        for (int cc = 0; cc < 16; cc++)
            dst[cc] = __floats2half2_rn(src[cc * 2], src[cc * 2 + 1]);
    }
}

// ---------------- GEMM: half [n x 64] @ [64 x 10] -> fp32 [n x 10] ----------------
__global__ void gemm_out10(const __half* __restrict__ A, const float* __restrict__ W,
                           float* __restrict__ C, int n) {
    __shared__ float Ws[64][10];
    __shared__ float As[16][257];
    int tid = threadIdx.x;
    for (int i = tid; i < 640; i += 256) Ws[i / 10][i % 10] = W[i];
    int n0 = blockIdx.x * 256;
    float acc[10];
    #pragma unroll
    for (int c = 0; c < 10; c++) acc[c] = 0.f;

    for (int k0 = 0; k0 < 64; k0 += 16) {
        #pragma unroll
        for (int i = 0; i < 2; i++) {
            int u = tid + i * 256;
            int node = u >> 1;
            int c8 = (u & 1) * 8;
            int gn = n0 + node;
            uint4 q = (gn < n)
                ? *reinterpret_cast<const uint4*>(A + (size_t)gn * 64 + k0 + c8)
                : make_uint4(0u, 0u, 0u, 0u);
            float2 f0 = __half22float2(*reinterpret_cast<__half2*>(&q.x));
            float2 f1 = __half22float2(*reinterpret_cast<__half2*>(&q.y));
            float2 f2 = __half22float2(*reinterpret_cast<__half2*>(&q.z));
            float2 f3 = __half22float2(*reinterpret_cast<__half2*>(&q.w));
            As[c8 + 0][node] = f0.x; As[c8 + 1][node] = f0.y;
            As[c8 + 2][node] = f1.x; As[c8 + 3][node] = f1.y;
            As[c8 + 4][node] = f2.x; As[c8 + 5][node] = f2.y;
            As[c8 + 6][node] = f3.x; As[c8 + 7][node] = f3.y;
        }
        __syncthreads();
        #pragma unroll
        for (int kk = 0; kk < 16; kk++) {
            float a = As[kk][tid];
            #pragma unroll
            for (int c = 0; c < 10; c++) acc[c] += a * Ws[k0 + kk][c];
        }
        __syncthreads();
    }
    int gn = n0 + tid;
    if (gn < n) {
        #pragma unroll
        for (int c = 0; c < 10; c++) C[(size_t)gn * 10 + c] = acc[c];
    }
}

// ---------------- propagation, 64 ch fp16 -> fp16: warp per node ----------------
__global__ void prop64(const __half* __restrict__ Hin, __half* __restrict__ Hout,
                       const float* __restrict__ bias, int n, int do_relu) {
    int gtid = blockIdx.x * blockDim.x + threadIdx.x;
    int v = gtid >> 5;
    int lane = threadIdx.x & 31;
    int wl = threadIdx.x >> 5;
    __shared__ int2 s_e[8][32];
    if (v >= n) return;

    float dv = g_dinv[v];
    float selfn = dv * dv;
    float2 xv = __half22float2(reinterpret_cast<const __half2*>(Hin + (size_t)v * 64)[lane]);
    float2 acc = make_float2(selfn * xv.x, selfn * xv.y);

    int e0 = g_rowptr[v], e1 = g_rowptr[v + 1];
    for (int base = e0; base < e1; base += 32) {
        int ne = min(32, e1 - base);
        if (lane < ne) s_e[wl][lane] = g_edge[base + lane];
        __syncwarp();
        #pragma unroll 8
        for (int j = 0; j < ne; j++) {
            int2 e = s_e[wl][j];
            float nm = __int_as_float(e.y);
            float2 hh = __half22float2(
                reinterpret_cast<const __half2*>(Hin + (size_t)e.x * 64)[lane]);
            acc.x += nm * hh.x;
            acc.y += nm * hh.y;
        }
        __syncwarp();
    }
    float2 b = reinterpret_cast<const float2*>(bias)[lane];
    acc.x += b.x; acc.y += b.y;
    if (do_relu) {
        acc.x = fmaxf(acc.x, 0.f);
        acc.y = fmaxf(acc.y, 0.f);
    }
    reinterpret_cast<__half2*>(Hout + (size_t)v * 64)[lane] = __floats2half2_rn(acc.x, acc.y);
}

// ---------------- propagation 10ch + fused mean-pool ----------------
__global__ void prop10_pool(const float* __restrict__ Hin, const float* __restrict__ bias,
                            const int* __restrict__ batch, int n) {
    int gtid = blockIdx.x * blockDim.x + threadIdx.x;
    int v = gtid >> 5;
    int lane = threadIdx.x & 31;
    int wl = threadIdx.x >> 5;
    __shared__ int2 s_e[8][32];
    if (v >= n) return;

    float dv = g_dinv[v];
    float selfn = dv * dv;
    float acc = 0.f;
    if (lane < NUM_CLASSES) acc = selfn * Hin[(size_t)v * 10 + lane];

    int e0 = g_rowptr[v], e1 = g_rowptr[v + 1];
    for (int base = e0; base < e1; base += 32) {
        int ne = min(32, e1 - base);
        if (lane < ne) s_e[wl][lane] = g_edge[base + lane];
        __syncwarp();
        #pragma unroll 4
        for (int j = 0; j < ne; j++) {
            int2 e = s_e[wl][j];
            float nm = __int_as_float(e.y);
            if (lane < NUM_CLASSES)
                acc += nm * Hin[(size_t)e.x * 10 + lane];
        }
        __syncwarp();
    }
    int g = batch[v];
    if (lane < NUM_CLASSES)
        atomicAdd(&g_pool[g * 10 + lane], acc + bias[lane]);
    if (lane == NUM_CLASSES)
        atomicAdd(&g_pcnt[g], 1.f);
}

// ---------------- final mean + log_softmax (self-restoring) ----------------
__global__ void final_kernel(float* __restrict__ out) {
    int g = threadIdx.x;
    if (g >= NUM_GRAPHS) return;
    float inv = 1.f / fmaxf(g_pcnt[g], 1.f);
    float v[NUM_CLASSES];
    float m = -1e30f;
    #pragma unroll
    for (int c = 0; c < NUM_CLASSES; c++) {
        v[c] = g_pool[g * 10 + c] * inv;
        m = fmaxf(m, v[c]);
    }
    float ssum = 0.f;
    #pragma unroll
    for (int c = 0; c < NUM_CLASSES; c++) ssum += expf(v[c] - m);
    float lse = m + logf(ssum);
    #pragma unroll
    for (int c = 0; c < NUM_CLASSES; c++) {
        out[g * 10 + c] = v[c] - lse;
        g_pool[g * 10 + c] = 0.f;
    }
    g_pcnt[g] = 0.f;
}

// ---------------- launch ----------------
extern "C" void kernel_launch(void* const* d_in, const int* in_sizes, int n_in,
                              void* d_out, int out_size) {
    const float* x   = (const float*)d_in[0];
    const int*   ei  = (const int*)d_in[1];
    const int*   bat = (const int*)d_in[2];
    const float* W1  = (const float*)d_in[3];
    const float* b1  = (const float*)d_in[4];
    const float* W2  = (const float*)d_in[5];
    const float* b2  = (const float*)d_in[6];
    const float* W3  = (const float*)d_in[7];
    const float* b3  = (const float*)d_in[8];
    float* out = (float*)d_out;

    __half* th = nullptr; __half* hh = nullptr; float* t10 = nullptr;
    void* p_look = nullptr;
    cudaGetSymbolAddress((void**)&th, g_th);
    cudaGetSymbolAddress((void**)&hh, g_hh);
    cudaGetSymbolAddress((void**)&t10, g_t10);
    cudaGetSymbolAddress(&p_look, g_look);

    static cudaStream_t s2 = nullptr;
    static cudaEvent_t evFork = nullptr, evJoin = nullptr;
    if (s2 == nullptr) {
        cudaStreamCreateWithFlags(&s2, cudaStreamNonBlocking);
        cudaEventCreateWithFlags(&evFork, cudaEventDisableTiming);
        cudaEventCreateWithFlags(&evJoin, cudaEventDisableTiming);
    }

    const int TB = 256;
    int nblk  = (N_NODES + TB - 1) / TB;
    int eblk  = (N_EDGES + TB - 1) / TB;
    int wblk  = (N_NODES * 32 + TB - 1) / TB;
    int gblk  = (N_NODES + 127) / 128;
    const size_t GSM = 8 * 32 * 36 * sizeof(float);   // 36864B (>= A+W staging)

    // ---- fork: CSR preprocessing on s2, GEMM-1 on main ----
    cudaEventRecord(evFork, 0);
    cudaStreamWaitEvent(s2, evFork, 0);

    cudaMemsetAsync(p_look, 0, SCAN_NBLK * sizeof(int), s2);
    count_kernel<<<eblk, TB, 0, s2>>>(ei);
    build_rowptr<<<SCAN_NBLK, SCAN_BS, 0, s2>>>();
    scatter_kernel<<<eblk, TB, 0, s2>>>(ei);
    cudaEventRecord(evJoin, s2);

    gemm64_hmma<IN_CH, float><<<gblk, TB, GSM>>>(x, W1, th, N_NODES);

    cudaStreamWaitEvent(0, evJoin, 0);

    prop64<<<wblk, TB>>>(th, hh, b1, N_NODES, 1);
    gemm64_hmma<HID, __half><<<gblk, TB, GSM>>>(hh, W2, th, N_NODES);
    prop64<<<wblk, TB>>>(th, hh, b2, N_NODES, 1);
    gemm_out10<<<nblk, TB>>>(hh, W3, t10, N_NODES);
    prop10_pool<<<wblk, TB>>>(t10, b3, bat, N_NODES);

    final_kernel<<<1, 64>>>(out);
}

// round 7
// speedup vs baseline: 1.1162x; 1.0509x over previous
#include <cuda_runtime.h>
#include <cuda_fp16.h>
#include <math.h>
#include <mma.h>

using namespace nvcuda;

#define N_NODES   100000
#define N_EDGES   1600000
#define NUM_GRAPHS 64
#define IN_CH     128
#define HID       64
#define NUM_CLASSES 10

#define SCAN_BS   256
#define SCAN_IT   4
#define SCAN_CHUNK (SCAN_BS * SCAN_IT)
#define SCAN_NBLK ((N_NODES + SCAN_CHUNK - 1) / SCAN_CHUNK)  // 98
#define LB_FLAG   (1 << 30)

// ---------------- scratch ----------------
__device__ int   g_cnt[N_NODES];            // zero-init; scatter restores to zero
__device__ float g_dinv[N_NODES];
__device__ int   g_rowptr[N_NODES + 1];
__device__ int2  g_edge[N_EDGES];
__device__ int   g_look[SCAN_NBLK];
__device__ __align__(16) __half g_W1h[IN_CH * HID];
__device__ __align__(16) __half g_W2h[HID * HID];
__device__ __align__(128) __half g_th[(size_t)N_NODES * HID];  // GEMM outputs
__device__ __align__(128) __half g_hh[(size_t)N_NODES * HID];  // prop outputs
__device__ __align__(128) float  g_t10[(size_t)N_NODES * NUM_CLASSES];
__device__ float g_pool[NUM_GRAPHS * NUM_CLASSES];  // zero-init; final restores
__device__ float g_pcnt[NUM_GRAPHS];

// ---------------- W -> half (once per call, trivial) ----------------
__global__ void wconv_kernel(const float* __restrict__ W1, const float* __restrict__ W2) {
    int i = blockIdx.x * blockDim.x + threadIdx.x;
    if (i < IN_CH * HID) g_W1h[i] = __float2half(W1[i]);
    if (i < HID * HID)   g_W2h[i] = __float2half(W2[i]);
}

// ---------------- degree count ----------------
__global__ void count_kernel(const int* __restrict__ ei) {
    int e = blockIdx.x * blockDim.x + threadIdx.x;
    if (e < N_EDGES) atomicAdd(&g_cnt[ei[N_EDGES + e]], 1);
}

// ---------------- fused dinv + exclusive scan (decoupled lookback) ----------------
__global__ void build_rowptr() {
    int b = blockIdx.x, t = threadIdx.x;
    int lane = t & 31, warp = t >> 5;
    int i0 = b * SCAN_CHUNK + t * SCAN_IT;
    int v[SCAN_IT]; int s = 0;
    #pragma unroll
    for (int i = 0; i < SCAN_IT; i++) {
        int idx = i0 + i;
        int c = 0;
        if (idx < N_NODES) {
            c = g_cnt[idx];
            g_dinv[idx] = rsqrtf((float)(c + 1));
        }
        s += c; v[i] = s;
    }
    int x = s;
    #pragma unroll
    for (int off = 1; off < 32; off <<= 1) {
        int y = __shfl_up_sync(0xffffffffu, x, off);
        if (lane >= off) x += y;
    }
    __shared__ int ws[8];
    __shared__ int s_base;
    if (lane == 31) ws[warp] = x;
    if (t == 0) s_base = 0;

    int contrib = 0;
    if (t < b) {
        volatile int* lk = (volatile int*)&g_look[t];
        int val = *lk;
        while (val < LB_FLAG) { __nanosleep(64); val = *lk; }
        contrib = val - LB_FLAG;
    }
    __syncthreads();
    if (warp == 0 && lane < 8) {
        int w = ws[lane];
        int iw = w;
        #pragma unroll
        for (int off = 1; off < 8; off <<= 1) {
            int y = __shfl_up_sync(0xffu, iw, off);
            if (lane >= off) iw += y;
        }
        ws[lane] = iw - w;
        if (lane == 7) atomicExch(&g_look[b], iw | LB_FLAG);
    }
    #pragma unroll
    for (int off = 16; off; off >>= 1) contrib += __shfl_down_sync(0xffffffffu, contrib, off);
    if (lane == 0 && contrib) atomicAdd(&s_base, contrib);
    __syncthreads();

    int excl = s_base + ws[warp] + (x - s);
    #pragma unroll
    for (int i = 0; i < SCAN_IT; i++) {
        int idx = i0 + i;
        if (idx < N_NODES) g_rowptr[idx + 1] = excl + v[i];
    }
    if (b == 0 && t == 0) g_rowptr[0] = 0;
}

// ---------------- CSR scatter ----------------
__global__ void scatter_kernel(const int* __restrict__ ei) {
    int e = blockIdx.x * blockDim.x + threadIdx.x;
    if (e < N_EDGES) {
        int s = ei[e];
        int d = ei[N_EDGES + e];
        int pos = g_rowptr[d] + atomicSub(&g_cnt[d], 1) - 1;
        g_edge[pos] = make_int2(s, __float_as_int(g_dinv[s] * g_dinv[d]));
    }
}

// ---------------- single-stage HMMA GEMM: [n x K] @ [K x 64] -> half [n x 64] ----------------
// block 256 thr = 8 warps (4 Mwarps x 2 Nwarps), tile 128 x 64.
// Entire A tile (128 x K) + entire W (K x 64, already half) staged once; ONE sync; K-loop from smem.
template <int K, typename TA>
__global__ void gemm64_hmma(const TA* __restrict__ A, const __half* __restrict__ Wh,
                            __half* __restrict__ C, int n) {
    constexpr int AST = K + 8;     // A smem stride (halves)
    extern __shared__ char smraw[];
    __half (*Ash)[AST] = reinterpret_cast<__half(*)[AST]>(smraw);
    __half (*Wsh)[72]  = reinterpret_cast<__half(*)[72]>(smraw + 128 * AST * 2);
    float* Cs = reinterpret_cast<float*>(smraw);
    int tid = threadIdx.x, wid = tid >> 5, lane = tid & 31;
    int wm = wid >> 1, wn = wid & 1;
    int n0 = blockIdx.x * 128;

    // stage W (already half): K*64 halves = K*8 uint4 units
    #pragma unroll
    for (int i = tid; i < K * 8; i += 256) {
        uint4 q = reinterpret_cast<const uint4*>(Wh)[i];
        int k = (i * 8) >> 6, c = (i * 8) & 63;
        *reinterpret_cast<uint4*>(&Wsh[k][c]) = q;
    }

    // stage A tile
    if constexpr (sizeof(TA) == 4) {
        #pragma unroll
        for (int i = 0; i < (128 * K / 4) / 256; i++) {
            int f4 = tid + i * 256;
            int r  = f4 / (K / 4);
            int c4 = (f4 % (K / 4)) * 4;
            int gr = n0 + r;
            float4 v = (gr < n)
                ? *reinterpret_cast<const float4*>((const float*)A + (size_t)gr * K + c4)
                : make_float4(0.f, 0.f, 0.f, 0.f);
            __half2* dst = reinterpret_cast<__half2*>(&Ash[r][c4]);
            dst[0] = __floats2half2_rn(v.x, v.y);
            dst[1] = __floats2half2_rn(v.z, v.w);
        }
    } else {
        #pragma unroll
        for (int i = 0; i < (128 * K / 8) / 256; i++) {
            int u = tid + i * 256;
            int r  = u / (K / 8);
            int c8 = (u % (K / 8)) * 8;
            int gr = n0 + r;
            uint4 q = (gr < n)
                ? *reinterpret_cast<const uint4*>((const __half*)A + (size_t)gr * K + c8)
                : make_uint4(0u, 0u, 0u, 0u);
            *reinterpret_cast<uint4*>(&Ash[r][c8]) = q;
        }
    }
    __syncthreads();

    wmma::fragment<wmma::accumulator, 16, 16, 16, float> cf[2][2];
    #pragma unroll
    for (int mm = 0; mm < 2; mm++)
        #pragma unroll
        for (int nn = 0; nn < 2; nn++)
            wmma::fill_fragment(cf[mm][nn], 0.0f);

    #pragma unroll
    for (int ks = 0; ks < K / 16; ks++) {
        wmma::fragment<wmma::matrix_a, 16, 16, 16, __half, wmma::row_major> af[2];
        wmma::fragment<wmma::matrix_b, 16, 16, 16, __half, wmma::row_major> bf[2];
        #pragma unroll
        for (int mm = 0; mm < 2; mm++)
            wmma::load_matrix_sync(af[mm], &Ash[wm * 32 + mm * 16][ks * 16], AST);
        #pragma unroll
        for (int nn = 0; nn < 2; nn++)
            wmma::load_matrix_sync(bf[nn], &Wsh[ks * 16][wn * 32 + nn * 16], 72);
        #pragma unroll
        for (int mm = 0; mm < 2; mm++)
            #pragma unroll
            for (int nn = 0; nn < 2; nn++)
                wmma::mma_sync(cf[mm][nn], af[mm], bf[nn], cf[mm][nn]);
    }
    __syncthreads();   // before reusing smem for epilogue

    float* Cw = Cs + wid * (32 * 36);
    #pragma unroll
    for (int mm = 0; mm < 2; mm++)
        #pragma unroll
        for (int nn = 0; nn < 2; nn++)
            wmma::store_matrix_sync(Cw + mm * 16 * 36 + nn * 16, cf[mm][nn], 36, wmma::mem_row_major);
    __syncwarp();

    int gr = n0 + wm * 32 + lane;
    if (gr < n) {
        __half2* dst = reinterpret_cast<__half2*>(C + (size_t)gr * 64 + wn * 32);
        const float* src = Cw + lane * 36;
        #pragma unroll
        for (int cc = 0; cc < 16; cc++)
            dst[cc] = __floats2half2_rn(src[cc * 2], src[cc * 2 + 1]);
    }
}

// ---------------- GEMM: half [n x 64] @ [64 x 10] -> fp32 [n x 10] ----------------
__global__ void gemm_out10(const __half* __restrict__ A, const float* __restrict__ W,
                           float* __restrict__ C, int n) {
    __shared__ float Ws[64][10];
    __shared__ float As[16][257];
    int tid = threadIdx.x;
    for (int i = tid; i < 640; i += 256) Ws[i / 10][i % 10] = W[i];
    int n0 = blockIdx.x * 256;
    float acc[10];
    #pragma unroll
    for (int c = 0; c < 10; c++) acc[c] = 0.f;

    for (int k0 = 0; k0 < 64; k0 += 16) {
        #pragma unroll
        for (int i = 0; i < 2; i++) {
            int u = tid + i * 256;
            int node = u >> 1;
            int c8 = (u & 1) * 8;
            int gn = n0 + node;
            uint4 q = (gn < n)
                ? *reinterpret_cast<const uint4*>(A + (size_t)gn * 64 + k0 + c8)
                : make_uint4(0u, 0u, 0u, 0u);
            float2 f0 = __half22float2(*reinterpret_cast<__half2*>(&q.x));
            float2 f1 = __half22float2(*reinterpret_cast<__half2*>(&q.y));
            float2 f2 = __half22float2(*reinterpret_cast<__half2*>(&q.z));
            float2 f3 = __half22float2(*reinterpret_cast<__half2*>(&q.w));
            As[c8 + 0][node] = f0.x; As[c8 + 1][node] = f0.y;
            As[c8 + 2][node] = f1.x; As[c8 + 3][node] = f1.y;
            As[c8 + 4][node] = f2.x; As[c8 + 5][node] = f2.y;
            As[c8 + 6][node] = f3.x; As[c8 + 7][node] = f3.y;
        }
        __syncthreads();
        #pragma unroll
        for (int kk = 0; kk < 16; kk++) {
            float a = As[kk][tid];
            #pragma unroll
            for (int c = 0; c < 10; c++) acc[c] += a * Ws[k0 + kk][c];
        }
        __syncthreads();
    }
    int gn = n0 + tid;
    if (gn < n) {
        #pragma unroll
        for (int c = 0; c < 10; c++) C[(size_t)gn * 10 + c] = acc[c];
    }
}

// ---------------- propagation, 64 ch fp16 -> fp16: warp per node, shfl broadcast ----------------
__global__ void prop64(const __half* __restrict__ Hin, __half* __restrict__ Hout,
                       const float* __restrict__ bias, int n, int do_relu) {
    int gtid = blockIdx.x * blockDim.x + threadIdx.x;
    int v = gtid >> 5;
    int lane = threadIdx.x & 31;
    if (v >= n) return;

    float dv = g_dinv[v];
    float selfn = dv * dv;
    float2 xv = __half22float2(reinterpret_cast<const __half2*>(Hin + (size_t)v * 64)[lane]);
    float2 acc = make_float2(selfn * xv.x, selfn * xv.y);

    int e0 = g_rowptr[v], e1 = g_rowptr[v + 1];
    for (int base = e0; base < e1; base += 32) {
        int ne = min(32, e1 - base);
        int2 e = make_int2(0, 0);
        if (lane < ne) e = g_edge[base + lane];
        #pragma unroll 8
        for (int j = 0; j < ne; j++) {
            int   src = __shfl_sync(0xffffffffu, e.x, j);
            float nm  = __int_as_float(__shfl_sync(0xffffffffu, e.y, j));
            float2 hh = __half22float2(
                reinterpret_cast<const __half2*>(Hin + (size_t)src * 64)[lane]);
            acc.x += nm * hh.x;
            acc.y += nm * hh.y;
        }
    }
    float2 b = reinterpret_cast<const float2*>(bias)[lane];
    acc.x += b.x; acc.y += b.y;
    if (do_relu) {
        acc.x = fmaxf(acc.x, 0.f);
        acc.y = fmaxf(acc.y, 0.f);
    }
    reinterpret_cast<__half2*>(Hout + (size_t)v * 64)[lane] = __floats2half2_rn(acc.x, acc.y);
}

// ---------------- propagation 10ch + fused mean-pool, shfl broadcast ----------------
__global__ void prop10_pool(const float* __restrict__ Hin, const float* __restrict__ bias,
                            const int* __restrict__ batch, int n) {
    int gtid = blockIdx.x * blockDim.x + threadIdx.x;
    int v = gtid >> 5;
    int lane = threadIdx.x & 31;
    if (v >= n) return;

    float dv = g_dinv[v];
    float selfn = dv * dv;
    float acc = 0.f;
    if (lane < NUM_CLASSES) acc = selfn * Hin[(size_t)v * 10 + lane];

    int e0 = g_rowptr[v], e1 = g_rowptr[v + 1];
    for (int base = e0; base < e1; base += 32) {
        int ne = min(32, e1 - base);
        int2 e = make_int2(0, 0);
        if (lane < ne) e = g_edge[base + lane];
        #pragma unroll 8
        for (int j = 0; j < ne; j++) {
            int   src = __shfl_sync(0xffffffffu, e.x, j);
            float nm  = __int_as_float(__shfl_sync(0xffffffffu, e.y, j));
            if (lane < NUM_CLASSES)
                acc += nm * Hin[(size_t)src * 10 + lane];
        }
    }
    int g = batch[v];
    if (lane < NUM_CLASSES)
        atomicAdd(&g_pool[g * 10 + lane], acc + bias[lane]);
    if (lane == NUM_CLASSES)
        atomicAdd(&g_pcnt[g], 1.f);
}

// ---------------- final mean + log_softmax (self-restoring) ----------------
__global__ void final_kernel(float* __restrict__ out) {
    int g = threadIdx.x;
    if (g >= NUM_GRAPHS) return;
    float inv = 1.f / fmaxf(g_pcnt[g], 1.f);
    float v[NUM_CLASSES];
    float m = -1e30f;
    #pragma unroll
    for (int c = 0; c < NUM_CLASSES; c++) {
        v[c] = g_pool[g * 10 + c] * inv;
        m = fmaxf(m, v[c]);
    }
    float ssum = 0.f;
    #pragma unroll
    for (int c = 0; c < NUM_CLASSES; c++) ssum += expf(v[c] - m);
    float lse = m + logf(ssum);
    #pragma unroll
    for (int c = 0; c < NUM_CLASSES; c++) {
        out[g * 10 + c] = v[c] - lse;
        g_pool[g * 10 + c] = 0.f;
    }
    g_pcnt[g] = 0.f;
}

// ---------------- launch ----------------
extern "C" void kernel_launch(void* const* d_in, const int* in_sizes, int n_in,
                              void* d_out, int out_size) {
    const float* x   = (const float*)d_in[0];
    const int*   ei  = (const int*)d_in[1];
    const int*   bat = (const int*)d_in[2];
    const float* W1  = (const float*)d_in[3];
    const float* b1  = (const float*)d_in[4];
    const float* W2  = (const float*)d_in[5];
    const float* b2  = (const float*)d_in[6];
    const float* W3  = (const float*)d_in[7];
    const float* b3  = (const float*)d_in[8];
    float* out = (float*)d_out;

    __half* th = nullptr; __half* hh = nullptr; float* t10 = nullptr;
    __half* w1h = nullptr; __half* w2h = nullptr;
    void* p_look = nullptr;
    cudaGetSymbolAddress((void**)&th, g_th);
    cudaGetSymbolAddress((void**)&hh, g_hh);
    cudaGetSymbolAddress((void**)&t10, g_t10);
    cudaGetSymbolAddress((void**)&w1h, g_W1h);
    cudaGetSymbolAddress((void**)&w2h, g_W2h);
    cudaGetSymbolAddress(&p_look, g_look);

    // smem sizes: A(128 x (K+8)) + W(K x 72) halves; epilogue needs 36864B
    const size_t GSM1 = (size_t)128 * (IN_CH + 8) * 2 + (size_t)IN_CH * 72 * 2;  // 53248
    const size_t GSM2_raw = (size_t)128 * (HID + 8) * 2 + (size_t)HID * 72 * 2;  // 27648
    const size_t GSM2 = GSM2_raw > 36864 ? GSM2_raw : 36864;

    static cudaStream_t s2 = nullptr;
    static cudaEvent_t evFork = nullptr, evJoin = nullptr;
    if (s2 == nullptr) {
        cudaStreamCreateWithFlags(&s2, cudaStreamNonBlocking);
        cudaEventCreateWithFlags(&evFork, cudaEventDisableTiming);
        cudaEventCreateWithFlags(&evJoin, cudaEventDisableTiming);
        cudaFuncSetAttribute(gemm64_hmma<IN_CH, float>,
                             cudaFuncAttributeMaxDynamicSharedMemorySize, (int)GSM1);
        cudaFuncSetAttribute(gemm64_hmma<HID, __half>,
                             cudaFuncAttributeMaxDynamicSharedMemorySize, (int)GSM2);
    }

    const int TB = 256;
    int nblk  = (N_NODES + TB - 1) / TB;
    int eblk  = (N_EDGES + TB - 1) / TB;
    int wblk  = (N_NODES * 32 + TB - 1) / TB;
    int gblk  = (N_NODES + 127) / 128;

    // ---- fork: CSR preprocessing on s2, W-convert + GEMM-1 on main ----
    cudaEventRecord(evFork, 0);
    cudaStreamWaitEvent(s2, evFork, 0);

    cudaMemsetAsync(p_look, 0, SCAN_NBLK * sizeof(int), s2);
    count_kernel<<<eblk, TB, 0, s2>>>(ei);
    build_rowptr<<<SCAN_NBLK, SCAN_BS, 0, s2>>>();
    scatter_kernel<<<eblk, TB, 0, s2>>>(ei);
    cudaEventRecord(evJoin, s2);

    wconv_kernel<<<(IN_CH * HID + TB - 1) / TB, TB>>>(W1, W2);
    gemm64_hmma<IN_CH, float><<<gblk, TB, GSM1>>>(x, w1h, th, N_NODES);

    cudaStreamWaitEvent(0, evJoin, 0);

    prop64<<<wblk, TB>>>(th, hh, b1, N_NODES, 1);
    gemm64_hmma<HID, __half><<<gblk, TB, GSM2>>>(hh, w2h, th, N_NODES);
    prop64<<<wblk, TB>>>(th, hh, b2, N_NODES, 1);
    gemm_out10<<<nblk, TB>>>(hh, W3, t10, N_NODES);
    prop10_pool<<<wblk, TB>>>(t10, b3, bat, N_NODES);

    final_kernel<<<1, 64>>>(out);
}